// round 16
// baseline (speedup 1.0000x reference)
#include <cuda_runtime.h>
#include <cstdint>

#define THRESH 0.85f
#define NB 4
#define ND 16
#define NN 4096
#define HS 32           // k32 steps per warp (K quarter = 1024)

__device__ __forceinline__ float cvt_tf32f(float x) {
    uint32_t u; asm("cvt.rna.tf32.f32 %0, %1;" : "=r"(u) : "f"(x));
    return __uint_as_float(u);
}
// threshold only; HMMA's tf32 datapath truncates low mantissa bits in HW
__device__ __forceinline__ uint32_t thr(float w) {
    float wt = (w > THRESH) ? w : 0.0f;
    return __float_as_uint(wt);
}
__device__ __forceinline__ void mma_tf32(float (&c)[4], uint32_t a0, uint32_t a1,
                                         uint32_t a2, uint32_t a3,
                                         uint32_t b0, uint32_t b1) {
    asm volatile(
        "mma.sync.aligned.m16n8k8.row.col.f32.tf32.tf32.f32 "
        "{%0,%1,%2,%3}, {%4,%5,%6,%7}, {%8,%9}, {%0,%1,%2,%3};"
        : "+f"(c[0]), "+f"(c[1]), "+f"(c[2]), "+f"(c[3])
        : "r"(a0), "r"(a1), "r"(a2), "r"(a3), "r"(b0), "r"(b1));
}
__device__ __forceinline__ uint32_t fu(float x) { return __float_as_uint(x); }
__device__ __forceinline__ float uf(uint32_t x) { return __uint_as_float(x); }

// ---------------- main (and only) kernel ----------------
// grid = 512 CTAs (4 b x 128 tiles of 32 m-rows), block = 256 thr = 8 warps.
// Warp w = (quarter q = w>>1, m-half h = w&1): rows m0+h*16..+15, K quarter
// [q*1024,(q+1)*1024) as 32 k32-steps. Computes D^T = S @ Wt^T via m16n8k8
// tf32 MMA: W thresholded in registers as the B operand (streaming __ldcs),
// A fragments loaded on the fly from seg as float2 pairs + cvt.rna (no
// precomputed table, no prologue kernel). Both operands double-buffered.
__global__ void __launch_bounds__(256, 2) regu_mma_kernel(const float* __restrict__ W,
                                                          const float* __restrict__ seg,
                                                          float* __restrict__ out) {
    __shared__ float sred[6][32][10];
    const int tid  = threadIdx.x;
    const int w    = tid >> 5;
    const int lane = tid & 31;
    const int gr   = lane >> 2;
    const int tg   = lane & 3;
    const int q    = w >> 1;             // K quarter
    const int h    = w & 1;              // m-half
    const int b    = blockIdx.x >> 7;
    const int m0   = ((blockIdx.x & 127) << 5) + h * 16;
    const int kq   = q << 10;

    // B-operand row pointers: lane (gr,tg) reads W rows m0+gr / m0+8+gr, slice 8*tg
    const float* Wb0 = W + ((size_t)(b * NN + m0 + gr)) * NN + kq + 8 * tg;
    const float* Wb1 = Wb0 + (size_t)8 * NN;
    // A-operand (seg) row pointers for fragment rows gr and gr+8
    const float* Sg0 = seg + (((size_t)b * ND + gr) << 12) + kq + 8 * tg;
    const float* Sg1 = Sg0 + ((size_t)8 << 12);

    float4 rW[2][4];   // [buf][nt*2+j]
    float4 rA[2][4];   // [buf][ks] = (a0,a1,a2,a3) tf32-rounded

#define LOAD_A(BUF, KO)                                                        \
    do {                                                                       \
        _Pragma("unroll")                                                      \
        for (int ks = 0; ks < 4; ++ks) {                                       \
            float2 fa = *reinterpret_cast<const float2*>(Sg0 + (KO) + 2 * ks); \
            float2 fb = *reinterpret_cast<const float2*>(Sg1 + (KO) + 2 * ks); \
            rA[BUF][ks].x = cvt_tf32f(fa.x);                                   \
            rA[BUF][ks].y = cvt_tf32f(fb.x);                                   \
            rA[BUF][ks].z = cvt_tf32f(fa.y);                                   \
            rA[BUF][ks].w = cvt_tf32f(fb.y);                                   \
        }                                                                      \
    } while (0)

#pragma unroll
    for (int j = 0; j < 2; ++j) {
        rW[0][j]     = __ldcs(reinterpret_cast<const float4*>(Wb0 + j * 4));
        rW[0][2 + j] = __ldcs(reinterpret_cast<const float4*>(Wb1 + j * 4));
    }
    LOAD_A(0, 0);

    float acc[2][4] = {{0.f,0.f,0.f,0.f},{0.f,0.f,0.f,0.f}};
    float rs0 = 0.f, rs1 = 0.f;

#pragma unroll 2
    for (int hs = 0; hs < HS; ++hs) {
        const int p  = hs & 1;
        const int hn = (hs + 1 < HS) ? hs + 1 : 0;   // harmless wrap on last iter
        // ---- prefetch h-step hn into the other buffer ----
        const float* wp0 = Wb0 + hn * 32;
        const float* wp1 = Wb1 + hn * 32;
#pragma unroll
        for (int j = 0; j < 2; ++j) {
            rW[p ^ 1][j]     = __ldcs(reinterpret_cast<const float4*>(wp0 + j * 4));
            rW[p ^ 1][2 + j] = __ldcs(reinterpret_cast<const float4*>(wp1 + j * 4));
        }
        LOAD_A(p ^ 1, hn * 32);
        // ---- compute on buffer p ----
        const float4 A0 = rA[p][0], A1 = rA[p][1], A2 = rA[p][2], A3 = rA[p][3];
#pragma unroll
        for (int nt = 0; nt < 2; ++nt) {
            const float4 f0 = rW[p][2 * nt], f1 = rW[p][2 * nt + 1];
            uint32_t t0 = thr(f0.x), t1 = thr(f0.y);
            uint32_t t2 = thr(f0.z), t3 = thr(f0.w);
            uint32_t t4 = thr(f1.x), t5 = thr(f1.y);
            uint32_t t6 = thr(f1.z), t7 = thr(f1.w);
            float s = ((uf(t0) + uf(t1)) + (uf(t2) + uf(t3))) +
                      ((uf(t4) + uf(t5)) + (uf(t6) + uf(t7)));
            if (nt == 0) rs0 += s; else rs1 += s;
            mma_tf32(acc[nt], fu(A0.x), fu(A0.y), fu(A0.z), fu(A0.w), t0, t1);
            mma_tf32(acc[nt], fu(A1.x), fu(A1.y), fu(A1.z), fu(A1.w), t2, t3);
            mma_tf32(acc[nt], fu(A2.x), fu(A2.y), fu(A2.z), fu(A2.w), t4, t5);
            mma_tf32(acc[nt], fu(A3.x), fu(A3.y), fu(A3.z), fu(A3.w), t6, t7);
        }
    }
#undef LOAD_A

    // rowsum quad-reduce: all lanes of quad gr end with rs(m = nt*8 + gr)
    rs0 += __shfl_xor_sync(0xffffffffu, rs0, 1);
    rs0 += __shfl_xor_sync(0xffffffffu, rs0, 2);
    rs1 += __shfl_xor_sync(0xffffffffu, rs1, 1);
    rs1 += __shfl_xor_sync(0xffffffffu, rs1, 2);

    // combine K-quarter partials: warps with q>0 publish; q==0 warps finalize.
    if (q > 0) {
        float* d = sred[(q - 1) * 2 + h][lane];
#pragma unroll
        for (int nt = 0; nt < 2; ++nt)
#pragma unroll
            for (int c = 0; c < 4; ++c) d[nt * 4 + c] = acc[nt][c];
        d[8] = rs0; d[9] = rs1;
    }
    __syncthreads();
    if (q == 0) {
#pragma unroll
        for (int s = 0; s < 3; ++s) {
            const float* sp = sred[s * 2 + h][lane];
#pragma unroll
            for (int nt = 0; nt < 2; ++nt)
#pragma unroll
                for (int c = 0; c < 4; ++c) acc[nt][c] += sp[nt * 4 + c];
            rs0 += sp[8]; rs1 += sp[9];
        }
        const float i00 = 1.0f / __shfl_sync(0xffffffffu, rs0, 8 * tg);
        const float i01 = 1.0f / __shfl_sync(0xffffffffu, rs0, 8 * tg + 4);
        const float i10 = 1.0f / __shfl_sync(0xffffffffu, rs1, 8 * tg);
        const float i11 = 1.0f / __shfl_sync(0xffffffffu, rs1, 8 * tg + 4);
        // acc[nt][c]: d = gr + 8*(c>=2), m = m0 + nt*8 + 2tg + (c&1)
        float* ob = out + (size_t)b * ND * NN;
#pragma unroll
        for (int nt = 0; nt < 2; ++nt) {
#pragma unroll
            for (int c = 0; c < 4; ++c) {
                const int dd = gr + ((c >= 2) ? 8 : 0);
                const int m  = m0 + nt * 8 + 2 * tg + (c & 1);
                const float inv = nt ? ((c & 1) ? i11 : i10)
                                     : ((c & 1) ? i01 : i00);
                ob[(size_t)dd * NN + m] = acc[nt][c] * inv;
            }
        }
    }
}

extern "C" void kernel_launch(void* const* d_in, const int* in_sizes, int n_in,
                              void* d_out, int out_size) {
    const float* seg = (const float*)d_in[0];   // [4,16,64,64] fp32
    const float* W   = (const float*)d_in[1];   // [4,4096,4096] fp32
    float* out = (float*)d_out;                 // [4,16,64,64] fp32
    (void)in_sizes; (void)n_in; (void)out_size;

    regu_mma_kernel<<<NB * (NN / 32), 256>>>(W, seg, out);
}

// round 17
// speedup vs baseline: 1.1236x; 1.1236x over previous
#include <cuda_runtime.h>
#include <cstdint>

#define THRESH 0.85f
#define NB 4
#define ND 16
#define NN 4096
#define HS 16           // k32 steps per warp (K eighth = 512)

// A-fragment table (S = tf32(seg), permuted k): [b][c32 0..127][ks 0..3][lane][4]
// physical k = c32*32 + 8*tg + 2*ks + (j>>1); row = gr + 8*(j&1). 1 MB, L2-resident.
__device__ float g_Afrag[NB * 128 * 4 * 32 * 4];

__device__ __forceinline__ uint32_t cvt_tf32(float x) {
    uint32_t u; asm("cvt.rna.tf32.f32 %0, %1;" : "=r"(u) : "f"(x));
    return u;
}
// threshold only; HMMA's tf32 datapath truncates low mantissa bits in HW
__device__ __forceinline__ uint32_t thr(float w) {
    float wt = (w > THRESH) ? w : 0.0f;
    return __float_as_uint(wt);
}
__device__ __forceinline__ void mma_tf32(float (&c)[4], uint32_t a0, uint32_t a1,
                                         uint32_t a2, uint32_t a3,
                                         uint32_t b0, uint32_t b1) {
    asm volatile(
        "mma.sync.aligned.m16n8k8.row.col.f32.tf32.tf32.f32 "
        "{%0,%1,%2,%3}, {%4,%5,%6,%7}, {%8,%9}, {%0,%1,%2,%3};"
        : "+f"(c[0]), "+f"(c[1]), "+f"(c[2]), "+f"(c[3])
        : "r"(a0), "r"(a1), "r"(a2), "r"(a3), "r"(b0), "r"(b1));
}
__device__ __forceinline__ uint32_t fu(float x) { return __float_as_uint(x); }
__device__ __forceinline__ float uf(uint32_t x) { return __uint_as_float(x); }

// ---------------- prologue: build permuted A-fragment table ----------------
__global__ void __launch_bounds__(256) build_afrag_kernel(const float* __restrict__ seg) {
    int idx  = blockIdx.x * 256 + threadIdx.x;    // [b][c][ks][lane], 65536 total
    int lane = idx & 31;
    int ks   = (idx >> 5) & 3;
    int c    = (idx >> 7) & 127;
    int b    = idx >> 14;
    int gr = lane >> 2, tg = lane & 3;
    int k  = c * 32 + 8 * tg + 2 * ks;
    const float* sp = seg + ((size_t)b * ND << 12);
    float4 v;
    v.x = uf(cvt_tf32(sp[((size_t)gr       << 12) + k]));
    v.y = uf(cvt_tf32(sp[((size_t)(gr + 8) << 12) + k]));
    v.z = uf(cvt_tf32(sp[((size_t)gr       << 12) + k + 1]));
    v.w = uf(cvt_tf32(sp[((size_t)(gr + 8) << 12) + k + 1]));
    reinterpret_cast<float4*>(g_Afrag)[idx] = v;
}

// ---------------- main kernel ----------------
// grid = 512 CTAs (4 b x 128 tiles of 32 m-rows), block = 256 thr = 8 warps.
// ALL 8 warps cover the same 32 rows; warp e owns K eighth [e*512,(e+1)*512)
// as 16 k32-steps (fully unrolled). Per step: 8 W-LDG.128 (__ldcs streaming,
// 3-buffer half-step ring) + 4 A-LDG.128 (table, double-buffered) + 16 MMA.
// A fragments are shared across 4 row-blocks (nt=0..3) -> A-side L2 traffic
// is HALVED vs the 16-row variant. Partials combined via smem at the end.
__global__ void __launch_bounds__(256, 2) regu_mma_kernel(const float* __restrict__ W,
                                                          float* __restrict__ out) {
    __shared__ float sred[7][32][20];
    const int tid  = threadIdx.x;
    const int w    = tid >> 5;           // K eighth
    const int lane = tid & 31;
    const int gr   = lane >> 2;
    const int tg   = lane & 3;
    const int b    = blockIdx.x >> 7;
    const int m0   = (blockIdx.x & 127) << 5;
    const int kq   = w << 9;

    // W base: lane (gr,tg) reads rows m0 + nt*8 + gr, 32B slice 8*tg of each k32
    const float* Wb = W + ((size_t)(b * NN + m0 + gr)) * NN + kq + 8 * tg;
    const float* Ab = g_Afrag + ((size_t)(b * 128 + (kq >> 5)) * 4) * 128 + lane * 4;

    float4 rw[3][4];   // half-step ring: [buf][{ntA j0, ntA j1, ntB j0, ntB j1}]
    float4 rA[2][4];   // A double buffer: [buf][ks]

#define LOAD_W(BUF, S, HF)                                                          \
    do {                                                                            \
        const float* p_ = Wb + (S) * 32 + (size_t)((HF) * 16) * NN;                 \
        rw[BUF][0] = __ldcs(reinterpret_cast<const float4*>(p_));                   \
        rw[BUF][1] = __ldcs(reinterpret_cast<const float4*>(p_ + 4));               \
        rw[BUF][2] = __ldcs(reinterpret_cast<const float4*>(p_ + (size_t)8 * NN));  \
        rw[BUF][3] = __ldcs(reinterpret_cast<const float4*>(p_ + (size_t)8 * NN + 4)); \
    } while (0)

#define LOAD_A(BUF, S)                                                              \
    do {                                                                            \
        const float* a_ = Ab + (size_t)(S) * 512;                                   \
        rA[BUF][0] = __ldg(reinterpret_cast<const float4*>(a_));                    \
        rA[BUF][1] = __ldg(reinterpret_cast<const float4*>(a_ + 128));              \
        rA[BUF][2] = __ldg(reinterpret_cast<const float4*>(a_ + 256));              \
        rA[BUF][3] = __ldg(reinterpret_cast<const float4*>(a_ + 384));              \
    } while (0)

    LOAD_W(0, 0, 0);      // lo half of step 0 (nt 0,1)
    LOAD_W(1, 0, 1);      // hi half of step 0 (nt 2,3)
    LOAD_A(0, 0);

    float acc[4][4];
#pragma unroll
    for (int nt = 0; nt < 4; ++nt)
#pragma unroll
        for (int c = 0; c < 4; ++c) acc[nt][c] = 0.0f;
    float rs[4] = {0.f, 0.f, 0.f, 0.f};

#define COMPUTE_HALF(BUF, P, NTB)                                                   \
    do {                                                                            \
        const float4 A0 = rA[P][0], A1 = rA[P][1], A2 = rA[P][2], A3 = rA[P][3];    \
        _Pragma("unroll")                                                           \
        for (int u = 0; u < 2; ++u) {                                               \
            const int nt = (NTB) + u;                                               \
            const float4 f0 = rw[BUF][2 * u], f1 = rw[BUF][2 * u + 1];              \
            uint32_t t0 = thr(f0.x), t1 = thr(f0.y);                                \
            uint32_t t2 = thr(f0.z), t3 = thr(f0.w);                                \
            uint32_t t4 = thr(f1.x), t5 = thr(f1.y);                                \
            uint32_t t6 = thr(f1.z), t7 = thr(f1.w);                                \
            rs[nt] += ((uf(t0) + uf(t1)) + (uf(t2) + uf(t3))) +                     \
                      ((uf(t4) + uf(t5)) + (uf(t6) + uf(t7)));                      \
            mma_tf32(acc[nt], fu(A0.x), fu(A0.y), fu(A0.z), fu(A0.w), t0, t1);      \
            mma_tf32(acc[nt], fu(A1.x), fu(A1.y), fu(A1.z), fu(A1.w), t2, t3);      \
            mma_tf32(acc[nt], fu(A2.x), fu(A2.y), fu(A2.z), fu(A2.w), t4, t5);      \
            mma_tf32(acc[nt], fu(A3.x), fu(A3.y), fu(A3.z), fu(A3.w), t6, t7);      \
        }                                                                           \
    } while (0)

    // fully unrolled: ring indices are compile-time constants
#pragma unroll
    for (int i = 0; i < HS; ++i) {
        const int p = i & 1;
        // ---- lo half (t = 2i): prefetch lo of step i+1 into buf (2i+2)%3 ----
        if (i + 1 < HS) LOAD_W((2 * i + 2) % 3, i + 1, 0);
        LOAD_A(p ^ 1, (i + 1 < HS) ? i + 1 : 0);
        COMPUTE_HALF((2 * i) % 3, p, 0);
        // ---- hi half (t = 2i+1): prefetch hi of step i+1 into buf (2i+3)%3 ----
        if (i + 1 < HS) LOAD_W((2 * i + 3) % 3, i + 1, 1);
        COMPUTE_HALF((2 * i + 1) % 3, p, 2);
    }
#undef LOAD_W
#undef LOAD_A
#undef COMPUTE_HALF

    // rowsum quad-reduce: all lanes of quad gr end with rs(m = m0 + nt*8 + gr)
#pragma unroll
    for (int nt = 0; nt < 4; ++nt) {
        rs[nt] += __shfl_xor_sync(0xffffffffu, rs[nt], 1);
        rs[nt] += __shfl_xor_sync(0xffffffffu, rs[nt], 2);
    }

    // combine K-eighth partials across the 8 warps
    if (w > 0) {
        float* d = sred[w - 1][lane];
#pragma unroll
        for (int nt = 0; nt < 4; ++nt) {
#pragma unroll
            for (int c = 0; c < 4; ++c) d[nt * 4 + c] = acc[nt][c];
            d[16 + nt] = rs[nt];
        }
    }
    __syncthreads();
    if (w == 0) {
#pragma unroll
        for (int s = 0; s < 7; ++s) {
            const float* sp = sred[s][lane];
#pragma unroll
            for (int nt = 0; nt < 4; ++nt) {
#pragma unroll
                for (int c = 0; c < 4; ++c) acc[nt][c] += sp[nt * 4 + c];
                rs[nt] += sp[16 + nt];
            }
        }
        // inverse rowsums for this lane's two output m-columns (2tg, 2tg+1)
        float inv[4][2];
#pragma unroll
        for (int nt = 0; nt < 4; ++nt) {
            inv[nt][0] = 1.0f / __shfl_sync(0xffffffffu, rs[nt], 8 * tg);
            inv[nt][1] = 1.0f / __shfl_sync(0xffffffffu, rs[nt], 8 * tg + 4);
        }
        // acc[nt][c]: d = gr + 8*(c>=2), m = m0 + nt*8 + 2tg + (c&1)
        float* ob = out + (size_t)b * ND * NN;
#pragma unroll
        for (int nt = 0; nt < 4; ++nt) {
#pragma unroll
            for (int c = 0; c < 4; ++c) {
                const int dd = gr + ((c >= 2) ? 8 : 0);
                const int m  = m0 + nt * 8 + 2 * tg + (c & 1);
                ob[(size_t)dd * NN + m] = acc[nt][c] * inv[nt][c & 1];
            }
        }
    }
}

extern "C" void kernel_launch(void* const* d_in, const int* in_sizes, int n_in,
                              void* d_out, int out_size) {
    const float* seg = (const float*)d_in[0];   // [4,16,64,64] fp32
    const float* W   = (const float*)d_in[1];   // [4,4096,4096] fp32
    float* out = (float*)d_out;                 // [4,16,64,64] fp32
    (void)in_sizes; (void)n_in; (void)out_size;

    build_afrag_kernel<<<256, 256>>>(seg);
    regu_mma_kernel<<<NB * (NN / 32), 256>>>(W, out);
}